// round 14
// baseline (speedup 1.0000x reference)
#include <cuda_runtime.h>
#include <cuda_fp16.h>
#include <cstdint>

#define NN 50000
#define NE 600000
#define NPAD 50176   // covers 391*128 = 50048 rows; pad rows stay zero

// ---------------- device-global scratch ------------------------------------
// INVARIANT: g_deg and g_ctr are zero at kernel_launch entry (zero-initialized
// at module load; restored by gs_offs / gs_fill each execution).
__device__ int    g_deg[NN];
__device__ int    g_deg2[NN];           // stable per-run copy of degrees
__device__ int    g_off[NN];
__device__ int    g_rank[NE];
__device__ int    g_ctr;
__device__ int    g_esrc[NE];
__device__ float  g_inv[NN];
__device__ __half g_featH[NN * 128];    // fp16 copy of feat
__device__ __half g_a[NPAD * 256];      // layer-1 GEMM input (fp16)
__device__ __half g_a2[NPAD * 256];     // relu(y1) unnormalized (fp16)
__device__ float  g_ssp[NN * 4];        // per-row sumsq partials (grid.y x wn)
__device__ __half g_w1[256 * 256];      // layer-1 weights, concat-K, fp16
__device__ __half g_w2[256 * 256];      // layer-2 weights, concat-N, fp16
__device__ __half g_ylh[NN * 128];      // GEMM2 yl out (fp16, gathered)
__device__ __half g_yrh[NN * 128];      // GEMM2 yr out (fp16)

// ---------------- small helpers --------------------------------------------
__device__ __forceinline__ uint32_t smem_u32(const void* p) {
    return (uint32_t)__cvta_generic_to_shared(p);
}
__device__ __forceinline__ void cp16(uint32_t dst, const void* src) {
    asm volatile("cp.async.cg.shared.global [%0], [%1], 16;" :: "r"(dst), "l"(src));
}
__device__ __forceinline__ void cp_commit() {
    asm volatile("cp.async.commit_group;");
}
template <int N> __device__ __forceinline__ void cp_wait() {
    asm volatile("cp.async.wait_group %0;" :: "n"(N));
}
__device__ __forceinline__ void ldm_x4(uint32_t* r, uint32_t addr) {
    asm volatile("ldmatrix.sync.aligned.m8n8.x4.shared.b16 {%0,%1,%2,%3}, [%4];"
                 : "=r"(r[0]), "=r"(r[1]), "=r"(r[2]), "=r"(r[3]) : "r"(addr));
}
__device__ __forceinline__ void mma_f16(float* c, const uint32_t* a, const uint32_t* b) {
    asm volatile("mma.sync.aligned.m16n8k16.row.col.f32.f16.f16.f32 "
                 "{%0,%1,%2,%3}, {%4,%5,%6,%7}, {%8,%9}, {%0,%1,%2,%3};"
                 : "+f"(c[0]), "+f"(c[1]), "+f"(c[2]), "+f"(c[3])
                 : "r"(a[0]), "r"(a[1]), "r"(a[2]), "r"(a[3]), "r"(b[0]), "r"(b[1]));
}

// accumulate one fp16 row (uint2 = 4 halves) into a float4
__device__ __forceinline__ void acc_row(float4& acc, uint2 u) {
    float2 a0 = __half22float2(*(__half2*)&u.x);
    float2 a1 = __half22float2(*(__half2*)&u.y);
    acc.x += a0.x; acc.y += a0.y; acc.z += a1.x; acc.w += a1.y;
}

// ------ init: fp16 weights + feat + edge histogram/rank (fused) -------------
__global__ void gs_init(const float* __restrict__ feat,
                        const int* __restrict__ ei,
                        const float* __restrict__ W1l, const float* __restrict__ W1r,
                        const float* __restrict__ W2l, const float* __restrict__ W2r) {
    int i = blockIdx.x * blockDim.x + threadIdx.x;
    if (i < NE) {
        int d = ei[NE + i];
        g_rank[i] = atomicAdd(&g_deg[d], 1);
    }
    if (i < 65536) {
        int n = i >> 8, k = i & 255;
        float w = (k < 128) ? W1l[n * 128 + k] : W1r[n * 128 + (k - 128)];
        g_w1[i] = __float2half_rn(w);
    } else if (i < 131072) {
        int j = i - 65536;
        int n = j >> 8, k = j & 255;
        float w = (n < 128) ? W2l[n * 256 + k] : W2r[(n - 128) * 256 + k];
        g_w2[j] = __float2half_rn(w);
    }
    if (i < NN * 64) {                       // feat: float2 -> half2
        float2 f = ((const float2*)feat)[i];
        ((__half2*)g_featH)[i] = __floats2half2_rn(f.x, f.y);
    }
}

// offs: scan degrees -> g_off; copy deg -> g_deg2; restore g_deg = 0
__global__ void gs_offs() {
    int n = blockIdx.x * blockDim.x + threadIdx.x;
    int lane = threadIdx.x & 31;
    int d = (n < NN) ? g_deg[n] : 0;
    int s = d;
    #pragma unroll
    for (int o = 1; o < 32; o <<= 1) {
        int t = __shfl_up_sync(0xffffffffu, s, o);
        if (lane >= o) s += t;
    }
    int tot = __shfl_sync(0xffffffffu, s, 31);
    int base = 0;
    if (lane == 0) base = atomicAdd(&g_ctr, tot);
    base = __shfl_sync(0xffffffffu, base, 0);
    if (n < NN) {
        g_off[n]  = base + s - d;
        g_deg2[n] = d;
        g_deg[n]  = 0;                       // restore invariant
    }
}

// fill: atomic-free via recorded rank; restore g_ctr = 0
__global__ void gs_fill(const int* __restrict__ ei) {
    int e = blockIdx.x * blockDim.x + threadIdx.x;
    if (e == 0) g_ctr = 0;                   // restore invariant
    if (e >= NE) return;
    int s = ei[e], d = ei[NE + e];
    g_esrc[g_off[d] + g_rank[e]] = s;
}

// ------ gather core: mean over CSR segment from fp16 matrix X[*,128] --------
__device__ __forceinline__ float4 gather_mean(const __half* __restrict__ X,
                                              int start, int deg, int lane,
                                              float inv) {
    float4 acc = make_float4(0.f, 0.f, 0.f, 0.f);
    for (int base = 0; base < deg; base += 32) {
        int cnt = min(deg - base, 32);
        int idx = (lane < cnt) ? g_esrc[start + base + lane] : 0;
        int j = 0;
        for (; j + 4 <= cnt; j += 4) {
            int s0 = __shfl_sync(0xffffffffu, idx, j);
            int s1 = __shfl_sync(0xffffffffu, idx, j + 1);
            int s2 = __shfl_sync(0xffffffffu, idx, j + 2);
            int s3 = __shfl_sync(0xffffffffu, idx, j + 3);
            uint2 u0 = *(const uint2*)(X + (size_t)s0 * 128 + lane * 4);
            uint2 u1 = *(const uint2*)(X + (size_t)s1 * 128 + lane * 4);
            uint2 u2 = *(const uint2*)(X + (size_t)s2 * 128 + lane * 4);
            uint2 u3 = *(const uint2*)(X + (size_t)s3 * 128 + lane * 4);
            acc_row(acc, u0); acc_row(acc, u1);
            acc_row(acc, u2); acc_row(acc, u3);
        }
        for (; j < cnt; ++j) {
            int s0 = __shfl_sync(0xffffffffu, idx, j);
            uint2 u0 = *(const uint2*)(X + (size_t)s0 * 128 + lane * 4);
            acc_row(acc, u0);
        }
    }
    acc.x *= inv; acc.y *= inv; acc.z *= inv; acc.w *= inv;
    return acc;
}

// ---------------- gather 1: mean(featH[nbrs]) + own featH -> fp16 A ---------
__global__ void gs_gather1() {
    int t = blockIdx.x * blockDim.x + threadIdx.x;
    int n = t >> 5;
    if (n >= NN) return;
    int lane = t & 31;
    int start = g_off[n], deg = g_deg2[n];

    float inv = 1.0f / fmaxf((float)deg, 1.0f);
    if (lane == 0) g_inv[n] = inv;
    float4 acc = gather_mean(g_featH, start, deg, lane, inv);

    size_t base = (size_t)n * 256 + lane * 4;
    ((__half2*)(g_a + base))[0] = __floats2half2_rn(acc.x, acc.y);
    ((__half2*)(g_a + base))[1] = __floats2half2_rn(acc.z, acc.w);
    uint2 own = *(const uint2*)(g_featH + (size_t)n * 128 + lane * 4);
    *(uint2*)(g_a + base + 128) = own;
}

// ---------------- pipelined fp16 GEMM: C = A @ W^T ---------------------------
// 128x128 CTA tile, 8 warps 4(m) x 2(n), warp tile 32x64, 3-stage cp.async.
// MODE 1: relu(y+b) -> g_a2 fp16 (unnormalized), sumsq(y+b) partials -> g_ssp.
// MODE 2: per-row scale = rsqrt(sum g_ssp) applied; yl -> g_ylh, yr -> g_yrh.
template <int MODE>
__global__ __launch_bounds__(256, 2)
void gs_gemm_pipe(const __half* __restrict__ A,
                  const __half* __restrict__ W,
                  const float* __restrict__ bias) {
    constexpr int STR = 40;
    constexpr int TSZ = 128 * STR;
    constexpr int STAGE = 2 * TSZ;
    extern __shared__ __half sm[];

    const int tid  = threadIdx.x;
    const int lane = tid & 31;
    const int warp = tid >> 5;
    const int wm   = warp >> 1;
    const int wn   = warp & 1;
    const int m0   = blockIdx.x * 128;
    const int n0   = blockIdx.y * 128;

    float c[2][8][4];
    #pragma unroll
    for (int a = 0; a < 2; ++a)
        #pragma unroll
        for (int b = 0; b < 8; ++b)
            #pragma unroll
            for (int k = 0; k < 4; ++k) c[a][b][k] = 0.f;

    auto issue_load = [&](int kt, int st) {
        const int k0 = kt * 32;
        __half* base = sm + st * STAGE;
        #pragma unroll
        for (int l = 0; l < 2; ++l) {
            int idx = tid + l * 256;
            int r   = idx >> 2;
            int cq  = (idx & 3) * 8;
            uint32_t ds = smem_u32(base + r * STR + cq);
            cp16(ds,           A + (size_t)(m0 + r) * 256 + k0 + cq);
            cp16(ds + TSZ * 2, W + (size_t)(n0 + r) * 256 + k0 + cq);
        }
        cp_commit();
    };

    issue_load(0, 0);
    issue_load(1, 1);

    for (int kt = 0; kt < 8; ++kt) {
        const int st = kt % 3;
        if (kt < 7) cp_wait<1>(); else cp_wait<0>();
        __syncthreads();
        if (kt + 2 < 8) issue_load(kt + 2, (kt + 2) % 3);

        const __half* As = sm + st * STAGE;
        const __half* Bs = As + TSZ;

        #pragma unroll
        for (int ks = 0; ks < 2; ++ks) {
            uint32_t ah[2][4];
            #pragma unroll
            for (int mi = 0; mi < 2; ++mi) {
                int r  = wm * 32 + mi * 16 + (lane & 15);
                int cc = ks * 16 + (lane >> 4) * 8;
                ldm_x4(ah[mi], smem_u32(As + r * STR + cc));
            }
            int mq = lane >> 3, ri = lane & 7;
            #pragma unroll
            for (int nip = 0; nip < 4; ++nip) {
                int row = wn * 64 + nip * 16 + (mq >> 1) * 8 + ri;
                int col = ks * 16 + (mq & 1) * 8;
                uint32_t b4[4];
                ldm_x4(b4, smem_u32(Bs + row * STR + col));
                #pragma unroll
                for (int mi = 0; mi < 2; ++mi) {
                    mma_f16(c[mi][2 * nip + 0], ah[mi], &b4[0]);
                    mma_f16(c[mi][2 * nip + 1], ah[mi], &b4[2]);
                }
            }
        }
    }

    float sc[2][2];
    if (MODE == 2) {
        #pragma unroll
        for (int mi = 0; mi < 2; ++mi)
            #pragma unroll
            for (int h = 0; h < 2; ++h) {
                int row = m0 + wm * 32 + mi * 16 + h * 8 + (lane >> 2);
                float s = 1.0f;
                if (row < NN) {
                    float ss = g_ssp[row * 4] + g_ssp[row * 4 + 1]
                             + g_ssp[row * 4 + 2] + g_ssp[row * 4 + 3];
                    s = 1.0f / fmaxf(sqrtf(ss), 1e-12f);
                }
                sc[mi][h] = s;
            }
    }

    float ss[2][2] = {{0.f, 0.f}, {0.f, 0.f}};
    #pragma unroll
    for (int mi = 0; mi < 2; ++mi) {
        int row = m0 + wm * 32 + mi * 16 + (lane >> 2);
        #pragma unroll
        for (int ni = 0; ni < 8; ++ni) {
            int col = n0 + wn * 64 + ni * 8 + (lane & 3) * 2;
            float2 v0 = make_float2(c[mi][ni][0], c[mi][ni][1]);
            float2 v1 = make_float2(c[mi][ni][2], c[mi][ni][3]);
            if (MODE == 1) {
                float b0 = bias[col], b1 = bias[col + 1];
                v0.x += b0; v0.y += b1;
                v1.x += b0; v1.y += b1;
                ss[mi][0] += v0.x * v0.x + v0.y * v0.y;
                ss[mi][1] += v1.x * v1.x + v1.y * v1.y;
                __half2 r0 = __floats2half2_rn(fmaxf(v0.x, 0.f), fmaxf(v0.y, 0.f));
                __half2 r1 = __floats2half2_rn(fmaxf(v1.x, 0.f), fmaxf(v1.y, 0.f));
                if (row < NN)     *(__half2*)(g_a2 + (size_t)row * 256 + col)       = r0;
                if (row + 8 < NN) *(__half2*)(g_a2 + (size_t)(row + 8) * 256 + col) = r1;
            } else {
                v0.x *= sc[mi][0]; v0.y *= sc[mi][0];
                v1.x *= sc[mi][1]; v1.y *= sc[mi][1];
                __half2 r0 = __floats2half2_rn(v0.x, v0.y);
                __half2 r1 = __floats2half2_rn(v1.x, v1.y);
                if (col < 128) {
                    if (row < NN)     *(__half2*)(g_ylh + (size_t)row * 128 + col)       = r0;
                    if (row + 8 < NN) *(__half2*)(g_ylh + (size_t)(row + 8) * 128 + col) = r1;
                } else {
                    if (row < NN)     *(__half2*)(g_yrh + (size_t)row * 128 + col - 128)       = r0;
                    if (row + 8 < NN) *(__half2*)(g_yrh + (size_t)(row + 8) * 128 + col - 128) = r1;
                }
            }
        }
    }

    if (MODE == 1) {
        int slot = blockIdx.y * 2 + wn;
        #pragma unroll
        for (int mi = 0; mi < 2; ++mi) {
            #pragma unroll
            for (int h = 0; h < 2; ++h) {
                float v = ss[mi][h];
                v += __shfl_xor_sync(0xffffffffu, v, 1);
                v += __shfl_xor_sync(0xffffffffu, v, 2);
                int row = m0 + wm * 32 + mi * 16 + h * 8 + (lane >> 2);
                if ((lane & 3) == 0 && row < NN) g_ssp[row * 4 + slot] = v;
            }
        }
    }
}

// ---------------- fused gather2 + final head --------------------------------
__global__ void gs_gather2_final(const float* __restrict__ b2,
                                 const float* __restrict__ Wfc,
                                 const float* __restrict__ bfc,
                                 float* __restrict__ out) {
    int t = blockIdx.x * blockDim.x + threadIdx.x;
    int n = t >> 5;
    if (n >= NN) return;
    int lane = t & 31;
    int start = g_off[n], deg = g_deg2[n];

    float inv = g_inv[n];
    float4 acc = gather_mean(g_ylh, start, deg, lane, inv);

    uint2 ur = *(const uint2*)(g_yrh + (size_t)n * 128 + lane * 4);
    float2 r0 = __half22float2(*(__half2*)&ur.x);
    float2 r1 = __half22float2(*(__half2*)&ur.y);
    float4 bb = *(const float4*)(b2 + lane * 4);
    float4 v;
    v.x = acc.x + r0.x + bb.x;
    v.y = acc.y + r0.y + bb.y;
    v.z = acc.z + r1.x + bb.z;
    v.w = acc.w + r1.y + bb.w;

    float s = v.x * v.x + v.y * v.y + v.z * v.z + v.w * v.w;
    #pragma unroll
    for (int o = 16; o > 0; o >>= 1) s += __shfl_xor_sync(0xffffffffu, s, o);
    float scale = 1.0f / fmaxf(sqrtf(s), 1e-12f);
    v.x *= scale; v.y *= scale; v.z *= scale; v.w *= scale;

    float4 w0 = *(const float4*)(Wfc + lane * 4);
    float4 w1 = *(const float4*)(Wfc + 128 + lane * 4);
    float l0 = v.x * w0.x + v.y * w0.y + v.z * w0.z + v.w * w0.w;
    float l1 = v.x * w1.x + v.y * w1.y + v.z * w1.z + v.w * w1.w;
    #pragma unroll
    for (int o = 16; o > 0; o >>= 1) {
        l0 += __shfl_xor_sync(0xffffffffu, l0, o);
        l1 += __shfl_xor_sync(0xffffffffu, l1, o);
    }
    if (lane == 0) {
        l0 += bfc[0]; l1 += bfc[1];
        float m  = fmaxf(l0, l1);
        float e0 = expf(l0 - m), e1 = expf(l1 - m);
        float d  = 1.0f / (e0 + e1);
        out[(size_t)n * 2 + 0] = e0 * d;
        out[(size_t)n * 2 + 1] = e1 * d;
    }
}

// ---------------- launch -----------------------------------------------------
extern "C" void kernel_launch(void* const* d_in, const int* in_sizes, int n_in,
                              void* d_out, int out_size) {
    const float* feat = (const float*)d_in[0];
    const int*   ei   = (const int*)d_in[1];
    const float* W1l  = (const float*)d_in[2];
    const float* b1   = (const float*)d_in[3];
    const float* W1r  = (const float*)d_in[4];
    const float* W2l  = (const float*)d_in[5];
    const float* b2   = (const float*)d_in[6];
    const float* W2r  = (const float*)d_in[7];
    const float* Wfc  = (const float*)d_in[8];
    const float* bfc  = (const float*)d_in[9];
    float* out = (float*)d_out;

    __half *p_w1, *p_w2, *p_a, *p_a2;
    cudaGetSymbolAddress((void**)&p_w1, g_w1);
    cudaGetSymbolAddress((void**)&p_w2, g_w2);
    cudaGetSymbolAddress((void**)&p_a,  g_a);
    cudaGetSymbolAddress((void**)&p_a2, g_a2);

    const int SMEM = 3 * 2 * 128 * 40 * 2;  // 3 stages x (A,B) = 61440 B
    cudaFuncSetAttribute(gs_gemm_pipe<1>, cudaFuncAttributeMaxDynamicSharedMemorySize, SMEM);
    cudaFuncSetAttribute(gs_gemm_pipe<2>, cudaFuncAttributeMaxDynamicSharedMemorySize, SMEM);

    // prologue (conversions + hist fused) + CSR build
    gs_init<<<(NN * 64 + 255) / 256, 256>>>(feat, ei, W1l, W1r, W2l, W2r);
    gs_offs<<<(NN + 255) / 256, 256>>>();
    gs_fill<<<(NE + 255) / 256, 256>>>(ei);

    // layer 1
    gs_gather1<<<(NN * 32 + 255) / 256, 256>>>();
    {
        dim3 grid((NN + 127) / 128, 2);
        gs_gemm_pipe<1><<<grid, 256, SMEM>>>(p_a, p_w1, b1);
    }

    // layer 2 (scale folded into epilogue)
    {
        dim3 grid((NN + 127) / 128, 2);
        gs_gemm_pipe<2><<<grid, 256, SMEM>>>(p_a2, p_w2, nullptr);
    }
    gs_gather2_final<<<(NN * 32 + 255) / 256, 256>>>(b2, Wfc, bfc, out);
}

// round 15
// speedup vs baseline: 1.0316x; 1.0316x over previous
#include <cuda_runtime.h>
#include <cuda_fp16.h>
#include <cstdint>

#define NN 50000
#define NE 600000
#define NPAD 50176   // covers 391*128 = 50048 rows; pad rows stay zero

// ---------------- device-global scratch ------------------------------------
// INVARIANT: g_deg and g_ctr are zero at kernel_launch entry (zero-initialized
// at module load; restored by gs_offs / gs_fill each execution).
__device__ int    g_deg[NN];
__device__ int    g_deg2[NN];           // stable per-run copy of degrees
__device__ int    g_off[NN];
__device__ int    g_rank[NE];
__device__ int    g_ctr;
__device__ int    g_esrc[NE];
__device__ float  g_inv[NN];
__device__ __half g_featH[NN * 128];    // fp16 copy of feat
__device__ __half g_a[NPAD * 256];      // layer-1 GEMM input (fp16)
__device__ __half g_a2[NPAD * 256];     // relu(y1) unnormalized (fp16)
__device__ float  g_ssp[NN * 4];        // per-row sumsq partials (grid.y x wn)
__device__ __half g_w1[256 * 256];      // layer-1 weights, concat-K, fp16
__device__ __half g_w2[256 * 256];      // layer-2 weights, concat-N, fp16
__device__ __half g_ylh[NN * 128];      // GEMM2 yl out (fp16, gathered)
__device__ __half g_yrh[NN * 128];      // GEMM2 yr out (fp16)

// ---------------- small helpers --------------------------------------------
__device__ __forceinline__ uint32_t smem_u32(const void* p) {
    return (uint32_t)__cvta_generic_to_shared(p);
}
__device__ __forceinline__ void cp16(uint32_t dst, const void* src) {
    asm volatile("cp.async.cg.shared.global [%0], [%1], 16;" :: "r"(dst), "l"(src));
}
__device__ __forceinline__ void cp_commit() {
    asm volatile("cp.async.commit_group;");
}
template <int N> __device__ __forceinline__ void cp_wait() {
    asm volatile("cp.async.wait_group %0;" :: "n"(N));
}
__device__ __forceinline__ void ldm_x4(uint32_t* r, uint32_t addr) {
    asm volatile("ldmatrix.sync.aligned.m8n8.x4.shared.b16 {%0,%1,%2,%3}, [%4];"
                 : "=r"(r[0]), "=r"(r[1]), "=r"(r[2]), "=r"(r[3]) : "r"(addr));
}
__device__ __forceinline__ void mma_f16(float* c, const uint32_t* a, const uint32_t* b) {
    asm volatile("mma.sync.aligned.m16n8k16.row.col.f32.f16.f16.f32 "
                 "{%0,%1,%2,%3}, {%4,%5,%6,%7}, {%8,%9}, {%0,%1,%2,%3};"
                 : "+f"(c[0]), "+f"(c[1]), "+f"(c[2]), "+f"(c[3])
                 : "r"(a[0]), "r"(a[1]), "r"(a[2]), "r"(a[3]), "r"(b[0]), "r"(b[1]));
}

// ------ init: fp16 weights + feat + edge histogram/rank (fused) -------------
__global__ void gs_init(const float* __restrict__ feat,
                        const int* __restrict__ ei,
                        const float* __restrict__ W1l, const float* __restrict__ W1r,
                        const float* __restrict__ W2l, const float* __restrict__ W2r) {
    int i = blockIdx.x * blockDim.x + threadIdx.x;
    if (i < NE) {
        int d = ei[NE + i];
        g_rank[i] = atomicAdd(&g_deg[d], 1);
    }
    if (i < 65536) {
        int n = i >> 8, k = i & 255;
        float w = (k < 128) ? W1l[n * 128 + k] : W1r[n * 128 + (k - 128)];
        g_w1[i] = __float2half_rn(w);
    } else if (i < 131072) {
        int j = i - 65536;
        int n = j >> 8, k = j & 255;
        float w = (n < 128) ? W2l[n * 256 + k] : W2r[(n - 128) * 256 + k];
        g_w2[j] = __float2half_rn(w);
    }
    if (i < NN * 64) {                       // feat: float2 -> half2
        float2 f = ((const float2*)feat)[i];
        ((__half2*)g_featH)[i] = __floats2half2_rn(f.x, f.y);
    }
}

// offs: scan degrees -> g_off; copy deg -> g_deg2; restore g_deg = 0
__global__ void gs_offs() {
    int n = blockIdx.x * blockDim.x + threadIdx.x;
    int lane = threadIdx.x & 31;
    int d = (n < NN) ? g_deg[n] : 0;
    int s = d;
    #pragma unroll
    for (int o = 1; o < 32; o <<= 1) {
        int t = __shfl_up_sync(0xffffffffu, s, o);
        if (lane >= o) s += t;
    }
    int tot = __shfl_sync(0xffffffffu, s, 31);
    int base = 0;
    if (lane == 0) base = atomicAdd(&g_ctr, tot);
    base = __shfl_sync(0xffffffffu, base, 0);
    if (n < NN) {
        g_off[n]  = base + s - d;
        g_deg2[n] = d;
        g_deg[n]  = 0;                       // restore invariant
    }
}

// fill: atomic-free via recorded rank; restore g_ctr = 0
__global__ void gs_fill(const int* __restrict__ ei) {
    int e = blockIdx.x * blockDim.x + threadIdx.x;
    if (e == 0) g_ctr = 0;                   // restore invariant
    if (e >= NE) return;
    int s = ei[e], d = ei[NE + e];
    g_esrc[g_off[d] + g_rank[e]] = s;
}

// ------ gather core: mean over CSR segment from fp16 matrix X[*,128] --------
// Pairwise fp16 adds halve the convert/FADD instruction count (issue-bound).
__device__ __forceinline__ float4 gather_mean(const __half* __restrict__ X,
                                              int start, int deg, int lane,
                                              float inv) {
    float4 acc = make_float4(0.f, 0.f, 0.f, 0.f);
    int i = 0;
    for (; i + 4 <= deg; i += 4) {
        int s0 = g_esrc[start + i];
        int s1 = g_esrc[start + i + 1];
        int s2 = g_esrc[start + i + 2];
        int s3 = g_esrc[start + i + 3];
        uint2 u0 = *(const uint2*)(X + (size_t)s0 * 128 + lane * 4);
        uint2 u1 = *(const uint2*)(X + (size_t)s1 * 128 + lane * 4);
        uint2 u2 = *(const uint2*)(X + (size_t)s2 * 128 + lane * 4);
        uint2 u3 = *(const uint2*)(X + (size_t)s3 * 128 + lane * 4);
        __half2 p0 = __hadd2(*(__half2*)&u0.x, *(__half2*)&u1.x);
        __half2 p1 = __hadd2(*(__half2*)&u0.y, *(__half2*)&u1.y);
        __half2 q0 = __hadd2(*(__half2*)&u2.x, *(__half2*)&u3.x);
        __half2 q1 = __hadd2(*(__half2*)&u2.y, *(__half2*)&u3.y);
        float2 f0 = __half22float2(p0), f1 = __half22float2(p1);
        float2 g0 = __half22float2(q0), g1 = __half22float2(q1);
        acc.x += f0.x + g0.x; acc.y += f0.y + g0.y;
        acc.z += f1.x + g1.x; acc.w += f1.y + g1.y;
    }
    if (i + 2 <= deg) {
        int s0 = g_esrc[start + i];
        int s1 = g_esrc[start + i + 1];
        uint2 u0 = *(const uint2*)(X + (size_t)s0 * 128 + lane * 4);
        uint2 u1 = *(const uint2*)(X + (size_t)s1 * 128 + lane * 4);
        __half2 p0 = __hadd2(*(__half2*)&u0.x, *(__half2*)&u1.x);
        __half2 p1 = __hadd2(*(__half2*)&u0.y, *(__half2*)&u1.y);
        float2 f0 = __half22float2(p0), f1 = __half22float2(p1);
        acc.x += f0.x; acc.y += f0.y; acc.z += f1.x; acc.w += f1.y;
        i += 2;
    }
    if (i < deg) {
        int s0 = g_esrc[start + i];
        uint2 u0 = *(const uint2*)(X + (size_t)s0 * 128 + lane * 4);
        float2 f0 = __half22float2(*(__half2*)&u0.x);
        float2 f1 = __half22float2(*(__half2*)&u0.y);
        acc.x += f0.x; acc.y += f0.y; acc.z += f1.x; acc.w += f1.y;
    }
    acc.x *= inv; acc.y *= inv; acc.z *= inv; acc.w *= inv;
    return acc;
}

// ---------------- gather 1: mean(featH[nbrs]) + own featH -> fp16 A ---------
__global__ void gs_gather1() {
    int t = blockIdx.x * blockDim.x + threadIdx.x;
    int n = t >> 5;
    if (n >= NN) return;
    int lane = t & 31;
    int start = g_off[n], deg = g_deg2[n];

    float inv = 1.0f / fmaxf((float)deg, 1.0f);
    if (lane == 0) g_inv[n] = inv;
    float4 acc = gather_mean(g_featH, start, deg, lane, inv);

    size_t base = (size_t)n * 256 + lane * 4;
    ((__half2*)(g_a + base))[0] = __floats2half2_rn(acc.x, acc.y);
    ((__half2*)(g_a + base))[1] = __floats2half2_rn(acc.z, acc.w);
    uint2 own = *(const uint2*)(g_featH + (size_t)n * 128 + lane * 4);
    *(uint2*)(g_a + base + 128) = own;
}

// ---------------- pipelined fp16 GEMM: C = A @ W^T ---------------------------
// 128x128 CTA tile, 8 warps 4(m) x 2(n), warp tile 32x64, 3-stage cp.async.
// MODE 1: relu(y+b) -> g_a2 fp16 (unnormalized), sumsq(y+b) partials -> g_ssp.
// MODE 2: per-row scale = rsqrt(sum g_ssp) applied; yl -> g_ylh, yr -> g_yrh.
template <int MODE>
__global__ __launch_bounds__(256, 2)
void gs_gemm_pipe(const __half* __restrict__ A,
                  const __half* __restrict__ W,
                  const float* __restrict__ bias) {
    constexpr int STR = 40;
    constexpr int TSZ = 128 * STR;
    constexpr int STAGE = 2 * TSZ;
    extern __shared__ __half sm[];

    const int tid  = threadIdx.x;
    const int lane = tid & 31;
    const int warp = tid >> 5;
    const int wm   = warp >> 1;
    const int wn   = warp & 1;
    const int m0   = blockIdx.x * 128;
    const int n0   = blockIdx.y * 128;

    float c[2][8][4];
    #pragma unroll
    for (int a = 0; a < 2; ++a)
        #pragma unroll
        for (int b = 0; b < 8; ++b)
            #pragma unroll
            for (int k = 0; k < 4; ++k) c[a][b][k] = 0.f;

    auto issue_load = [&](int kt, int st) {
        const int k0 = kt * 32;
        __half* base = sm + st * STAGE;
        #pragma unroll
        for (int l = 0; l < 2; ++l) {
            int idx = tid + l * 256;
            int r   = idx >> 2;
            int cq  = (idx & 3) * 8;
            uint32_t ds = smem_u32(base + r * STR + cq);
            cp16(ds,           A + (size_t)(m0 + r) * 256 + k0 + cq);
            cp16(ds + TSZ * 2, W + (size_t)(n0 + r) * 256 + k0 + cq);
        }
        cp_commit();
    };

    issue_load(0, 0);
    issue_load(1, 1);

    for (int kt = 0; kt < 8; ++kt) {
        const int st = kt % 3;
        if (kt < 7) cp_wait<1>(); else cp_wait<0>();
        __syncthreads();
        if (kt + 2 < 8) issue_load(kt + 2, (kt + 2) % 3);

        const __half* As = sm + st * STAGE;
        const __half* Bs = As + TSZ;

        #pragma unroll
        for (int ks = 0; ks < 2; ++ks) {
            uint32_t ah[2][4];
            #pragma unroll
            for (int mi = 0; mi < 2; ++mi) {
                int r  = wm * 32 + mi * 16 + (lane & 15);
                int cc = ks * 16 + (lane >> 4) * 8;
                ldm_x4(ah[mi], smem_u32(As + r * STR + cc));
            }
            int mq = lane >> 3, ri = lane & 7;
            #pragma unroll
            for (int nip = 0; nip < 4; ++nip) {
                int row = wn * 64 + nip * 16 + (mq >> 1) * 8 + ri;
                int col = ks * 16 + (mq & 1) * 8;
                uint32_t b4[4];
                ldm_x4(b4, smem_u32(Bs + row * STR + col));
                #pragma unroll
                for (int mi = 0; mi < 2; ++mi) {
                    mma_f16(c[mi][2 * nip + 0], ah[mi], &b4[0]);
                    mma_f16(c[mi][2 * nip + 1], ah[mi], &b4[2]);
                }
            }
        }
    }

    float sc[2][2];
    if (MODE == 2) {
        #pragma unroll
        for (int mi = 0; mi < 2; ++mi)
            #pragma unroll
            for (int h = 0; h < 2; ++h) {
                int row = m0 + wm * 32 + mi * 16 + h * 8 + (lane >> 2);
                float s = 1.0f;
                if (row < NN) {
                    float ss = g_ssp[row * 4] + g_ssp[row * 4 + 1]
                             + g_ssp[row * 4 + 2] + g_ssp[row * 4 + 3];
                    s = 1.0f / fmaxf(sqrtf(ss), 1e-12f);
                }
                sc[mi][h] = s;
            }
    }

    float ss[2][2] = {{0.f, 0.f}, {0.f, 0.f}};
    #pragma unroll
    for (int mi = 0; mi < 2; ++mi) {
        int row = m0 + wm * 32 + mi * 16 + (lane >> 2);
        #pragma unroll
        for (int ni = 0; ni < 8; ++ni) {
            int col = n0 + wn * 64 + ni * 8 + (lane & 3) * 2;
            float2 v0 = make_float2(c[mi][ni][0], c[mi][ni][1]);
            float2 v1 = make_float2(c[mi][ni][2], c[mi][ni][3]);
            if (MODE == 1) {
                float b0 = bias[col], b1 = bias[col + 1];
                v0.x += b0; v0.y += b1;
                v1.x += b0; v1.y += b1;
                ss[mi][0] += v0.x * v0.x + v0.y * v0.y;
                ss[mi][1] += v1.x * v1.x + v1.y * v1.y;
                __half2 r0 = __floats2half2_rn(fmaxf(v0.x, 0.f), fmaxf(v0.y, 0.f));
                __half2 r1 = __floats2half2_rn(fmaxf(v1.x, 0.f), fmaxf(v1.y, 0.f));
                if (row < NN)     *(__half2*)(g_a2 + (size_t)row * 256 + col)       = r0;
                if (row + 8 < NN) *(__half2*)(g_a2 + (size_t)(row + 8) * 256 + col) = r1;
            } else {
                v0.x *= sc[mi][0]; v0.y *= sc[mi][0];
                v1.x *= sc[mi][1]; v1.y *= sc[mi][1];
                __half2 r0 = __floats2half2_rn(v0.x, v0.y);
                __half2 r1 = __floats2half2_rn(v1.x, v1.y);
                if (col < 128) {
                    if (row < NN)     *(__half2*)(g_ylh + (size_t)row * 128 + col)       = r0;
                    if (row + 8 < NN) *(__half2*)(g_ylh + (size_t)(row + 8) * 128 + col) = r1;
                } else {
                    if (row < NN)     *(__half2*)(g_yrh + (size_t)row * 128 + col - 128)       = r0;
                    if (row + 8 < NN) *(__half2*)(g_yrh + (size_t)(row + 8) * 128 + col - 128) = r1;
                }
            }
        }
    }

    if (MODE == 1) {
        int slot = blockIdx.y * 2 + wn;
        #pragma unroll
        for (int mi = 0; mi < 2; ++mi) {
            #pragma unroll
            for (int h = 0; h < 2; ++h) {
                float v = ss[mi][h];
                v += __shfl_xor_sync(0xffffffffu, v, 1);
                v += __shfl_xor_sync(0xffffffffu, v, 2);
                int row = m0 + wm * 32 + mi * 16 + h * 8 + (lane >> 2);
                if ((lane & 3) == 0 && row < NN) g_ssp[row * 4 + slot] = v;
            }
        }
    }
}

// ---------------- fused gather2 + final head --------------------------------
__global__ void gs_gather2_final(const float* __restrict__ b2,
                                 const float* __restrict__ Wfc,
                                 const float* __restrict__ bfc,
                                 float* __restrict__ out) {
    int t = blockIdx.x * blockDim.x + threadIdx.x;
    int n = t >> 5;
    if (n >= NN) return;
    int lane = t & 31;
    int start = g_off[n], deg = g_deg2[n];

    float inv = g_inv[n];
    float4 acc = gather_mean(g_ylh, start, deg, lane, inv);

    uint2 ur = *(const uint2*)(g_yrh + (size_t)n * 128 + lane * 4);
    float2 r0 = __half22float2(*(__half2*)&ur.x);
    float2 r1 = __half22float2(*(__half2*)&ur.y);
    float4 bb = *(const float4*)(b2 + lane * 4);
    float4 v;
    v.x = acc.x + r0.x + bb.x;
    v.y = acc.y + r0.y + bb.y;
    v.z = acc.z + r1.x + bb.z;
    v.w = acc.w + r1.y + bb.w;

    float s = v.x * v.x + v.y * v.y + v.z * v.z + v.w * v.w;
    #pragma unroll
    for (int o = 16; o > 0; o >>= 1) s += __shfl_xor_sync(0xffffffffu, s, o);
    float scale = 1.0f / fmaxf(sqrtf(s), 1e-12f);
    v.x *= scale; v.y *= scale; v.z *= scale; v.w *= scale;

    float4 w0 = *(const float4*)(Wfc + lane * 4);
    float4 w1 = *(const float4*)(Wfc + 128 + lane * 4);
    float l0 = v.x * w0.x + v.y * w0.y + v.z * w0.z + v.w * w0.w;
    float l1 = v.x * w1.x + v.y * w1.y + v.z * w1.z + v.w * w1.w;
    #pragma unroll
    for (int o = 16; o > 0; o >>= 1) {
        l0 += __shfl_xor_sync(0xffffffffu, l0, o);
        l1 += __shfl_xor_sync(0xffffffffu, l1, o);
    }
    if (lane == 0) {
        l0 += bfc[0]; l1 += bfc[1];
        float m  = fmaxf(l0, l1);
        float e0 = expf(l0 - m), e1 = expf(l1 - m);
        float d  = 1.0f / (e0 + e1);
        out[(size_t)n * 2 + 0] = e0 * d;
        out[(size_t)n * 2 + 1] = e1 * d;
    }
}

// ---------------- launch -----------------------------------------------------
extern "C" void kernel_launch(void* const* d_in, const int* in_sizes, int n_in,
                              void* d_out, int out_size) {
    const float* feat = (const float*)d_in[0];
    const int*   ei   = (const int*)d_in[1];
    const float* W1l  = (const float*)d_in[2];
    const float* b1   = (const float*)d_in[3];
    const float* W1r  = (const float*)d_in[4];
    const float* W2l  = (const float*)d_in[5];
    const float* b2   = (const float*)d_in[6];
    const float* W2r  = (const float*)d_in[7];
    const float* Wfc  = (const float*)d_in[8];
    const float* bfc  = (const float*)d_in[9];
    float* out = (float*)d_out;

    __half *p_w1, *p_w2, *p_a, *p_a2;
    cudaGetSymbolAddress((void**)&p_w1, g_w1);
    cudaGetSymbolAddress((void**)&p_w2, g_w2);
    cudaGetSymbolAddress((void**)&p_a,  g_a);
    cudaGetSymbolAddress((void**)&p_a2, g_a2);

    const int SMEM = 3 * 2 * 128 * 40 * 2;  // 3 stages x (A,B) = 61440 B
    cudaFuncSetAttribute(gs_gemm_pipe<1>, cudaFuncAttributeMaxDynamicSharedMemorySize, SMEM);
    cudaFuncSetAttribute(gs_gemm_pipe<2>, cudaFuncAttributeMaxDynamicSharedMemorySize, SMEM);

    // prologue (conversions + hist fused) + CSR build
    gs_init<<<(NN * 64 + 255) / 256, 256>>>(feat, ei, W1l, W1r, W2l, W2r);
    gs_offs<<<(NN + 255) / 256, 256>>>();
    gs_fill<<<(NE + 255) / 256, 256>>>(ei);

    // layer 1
    gs_gather1<<<(NN * 32 + 255) / 256, 256>>>();
    {
        dim3 grid((NN + 127) / 128, 2);
        gs_gemm_pipe<1><<<grid, 256, SMEM>>>(p_a, p_w1, b1);
    }

    // layer 2 (scale folded into epilogue)
    {
        dim3 grid((NN + 127) / 128, 2);
        gs_gemm_pipe<2><<<grid, 256, SMEM>>>(p_a2, p_w2, nullptr);
    }
    gs_gather2_final<<<(NN * 32 + 255) / 256, 256>>>(b2, Wfc, bfc, out);
}